// round 13
// baseline (speedup 1.0000x reference)
#include <cuda_runtime.h>
#include <cuda_bf16.h>
#include <cstdint>

#define NODES_MAX 100000
#define DIM 128

typedef unsigned int u32;

// Scratch (allocation-free rule: __device__ globals)
__device__ float g_h[(size_t)NODES_MAX * DIM];     // relu(x@W0^T+b0)
__device__ float g_agg[(size_t)NODES_MAX * DIM];   // scatter-add accumulator
__device__ float g_deg[NODES_MAX];                 // degree accumulator

// ---------------- smem layout (bytes) ----------------
#define OFF_BIAS 0            // 128 f32
#define OFF_WC   512          // 512 f32
#define OFF_BC   2560         // 4 f32
#define OFF_INVD 2576         // 64 f32
#define OFF_CP   4096         // 4KB classifier cross-warp partials (4 ng x 64 x 4)
#define OFF_AH   8192         // 16KB (64x128 bf16)
#define OFF_AL   24576        // 16KB
#define OFF_BH   40960        // 32KB (128x128 bf16)
#define OFF_BL   73728        // 32KB
#define SMEM_BYTES 106496

// ---------------- helpers ----------------
__device__ __forceinline__ u32 smem_u32(const void* p) {
    u32 a;
    asm("{ .reg .u64 t; cvta.to.shared.u64 t, %1; cvt.u32.u64 %0, t; }" : "=r"(a) : "l"(p));
    return a;
}

__device__ __forceinline__ void ldsm_x4(u32* r, u32 addr) {
    asm volatile("ldmatrix.sync.aligned.m8n8.x4.shared.b16 {%0,%1,%2,%3}, [%4];"
                 : "=r"(r[0]), "=r"(r[1]), "=r"(r[2]), "=r"(r[3]) : "r"(addr));
}

__device__ __forceinline__ void mma_bf16(float* d, const u32* a, u32 b0, u32 b1) {
    asm volatile(
        "mma.sync.aligned.m16n8k16.row.col.f32.bf16.bf16.f32 "
        "{%0,%1,%2,%3}, {%4,%5,%6,%7}, {%8,%9}, {%0,%1,%2,%3};"
        : "+f"(d[0]), "+f"(d[1]), "+f"(d[2]), "+f"(d[3])
        : "r"(a[0]), "r"(a[1]), "r"(a[2]), "r"(a[3]), "r"(b0), "r"(b1));
}

// byte offset of 16B chunk (row, c8) in a 256B-pitch tile, XOR-8 swizzle
__device__ __forceinline__ u32 tile_off(int row, int c8) {
    return (u32)(row * 256 + (((c8 >> 3) ^ (row & 7)) << 4));
}

// hi/lo bf16 split of 8 floats -> one 16B store into each of two tiles
__device__ __forceinline__ void split_store(char* smb, int hi_off, int lo_off,
                                            u32 sw, const float* v) {
    u32 h[4], l[4];
#pragma unroll
    for (int j = 0; j < 4; j++) {
        float2 f = make_float2(v[2*j], v[2*j+1]);
        __nv_bfloat162 hb = __float22bfloat162_rn(f);
        float2 hf = __bfloat1622float2(hb);
        float2 r = make_float2(f.x - hf.x, f.y - hf.y);
        __nv_bfloat162 lb = __float22bfloat162_rn(r);
        h[j] = *(u32*)&hb;
        l[j] = *(u32*)&lb;
    }
    *(uint4*)(smb + hi_off + sw) = make_uint4(h[0], h[1], h[2], h[3]);
    *(uint4*)(smb + lo_off + sw) = make_uint4(l[0], l[1], l[2], l[3]);
}

// stage B = W (128x128, split bf16), 256 threads
__device__ __forceinline__ void stage_B(char* sm, const float* __restrict__ W, int tid) {
#pragma unroll
    for (int s = 0; s < 8; s++) {
        const int chunk = tid + s * 256;
        const int row = chunk >> 4, c8 = (chunk & 15) << 3;
        const u32 sw = tile_off(row, c8);
        float w[8];
        float4 w0 = *(const float4*)(W + row * DIM + c8);
        float4 w1 = *(const float4*)(W + row * DIM + c8 + 4);
        w[0]=w0.x; w[1]=w0.y; w[2]=w0.z; w[3]=w0.w;
        w[4]=w1.x; w[5]=w1.y; w[6]=w1.z; w[7]=w1.w;
        split_store(sm, OFF_BH, OFF_BL, sw, w);
    }
}

// mainloop: warp tile 32m x 32n. mt = m-half (0..1), ng = n-quarter (0..3).
// Per kk per warp: 4 a-LDSM + 4 b-LDSM for 24 MMAs (CTA total 64 LDSM/kk).
__device__ __forceinline__ void mainloop_32x32(float acc[2][4][4], u32 sb,
                                               int mt, int ng, int lane) {
    const int l7     = lane & 7;
    const int a_sel  = lane >> 4;
    const int b_rowl = l7 + ((lane >> 4) << 3);
    const int b_sel  = (lane >> 3) & 1;
    const int arow0  = mt * 32 + (lane & 15);

    u32 aH[2][4], aL[2][4], bH[2][4], bL[2][4];
#pragma unroll
    for (int kk = 0; kk < 8; kk++) {
        const u32 ao = (u32)(((2 * kk + a_sel) ^ l7) << 4);
        const u32 bo = (u32)(((2 * kk + b_sel) ^ l7) << 4);
#pragma unroll
        for (int at = 0; at < 2; at++) {
            const u32 ar = (u32)((arow0 + at * 16) * 256);
            ldsm_x4(aH[at], sb + OFF_AH + ar + ao);
            ldsm_x4(aL[at], sb + OFF_AL + ar + ao);
        }
#pragma unroll
        for (int g = 0; g < 2; g++) {
            const u32 br = (u32)((ng * 32 + g * 16 + b_rowl) * 256);
            ldsm_x4(bH[g], sb + OFF_BH + br + bo);
            ldsm_x4(bL[g], sb + OFF_BL + br + bo);
        }
#pragma unroll
        for (int at = 0; at < 2; at++)
#pragma unroll
            for (int g = 0; g < 2; g++) {
                mma_bf16(acc[at][2*g],   aH[at], bH[g][0], bH[g][1]);
                mma_bf16(acc[at][2*g+1], aH[at], bH[g][2], bH[g][3]);
                mma_bf16(acc[at][2*g],   aH[at], bL[g][0], bL[g][1]);
                mma_bf16(acc[at][2*g+1], aH[at], bL[g][2], bL[g][3]);
                mma_bf16(acc[at][2*g],   aL[at], bH[g][0], bH[g][1]);
                mma_bf16(acc[at][2*g+1], aL[at], bH[g][2], bH[g][3]);
            }
    }
}

// ---------------------------------------------------------------------------
// GEMM0: h = relu(x @ W0^T + b0). CTA 64x128, 256 threads, warps 2m x 4n.
// Also zeroes g_agg for this CTA's rows (replaces the 51MB memset).
// ---------------------------------------------------------------------------
__global__ __launch_bounds__(256, 2) void gemm0_mma(
    const float* __restrict__ A, const float* __restrict__ W,
    const float* __restrict__ bias, float* __restrict__ C, int n)
{
    extern __shared__ char sm[];
    const u32 sb = smem_u32(sm);
    const int tid = threadIdx.x, wid = tid >> 5, lane = tid & 31;
    const int R0 = blockIdx.x * 64;

    if (tid < 128) ((float*)(sm + OFF_BIAS))[tid] = bias[tid];

    // zero this CTA's g_agg rows (128B per thread, streaming)
    {
        const int zr = R0 + (tid >> 2);
        if (zr < n) {
            float4* d = (float4*)(g_agg + (size_t)zr * DIM + (tid & 3) * 32);
            const float4 z = make_float4(0.f, 0.f, 0.f, 0.f);
#pragma unroll
            for (int q = 0; q < 8; q++) d[q] = z;
        }
    }

    // stage A (64x128, split bf16)
#pragma unroll
    for (int s = 0; s < 4; s++) {
        const int chunk = tid + s * 256;
        const int row = chunk >> 4, c8 = (chunk & 15) << 3;
        const u32 sw = tile_off(row, c8);
        float v[8];
        const int gr = R0 + row;
        if (gr < n) {
            float4 a0 = *(const float4*)(A + (size_t)gr * DIM + c8);
            float4 a1 = *(const float4*)(A + (size_t)gr * DIM + c8 + 4);
            v[0]=a0.x; v[1]=a0.y; v[2]=a0.z; v[3]=a0.w;
            v[4]=a1.x; v[5]=a1.y; v[6]=a1.z; v[7]=a1.w;
        } else {
#pragma unroll
            for (int j = 0; j < 8; j++) v[j] = 0.f;
        }
        split_store(sm, OFF_AH, OFF_AL, sw, v);
    }
    stage_B(sm, W, tid);
    __syncthreads();

    float acc[2][4][4];
#pragma unroll
    for (int at = 0; at < 2; at++)
#pragma unroll
        for (int j = 0; j < 4; j++)
#pragma unroll
            for (int q = 0; q < 4; q++) acc[at][j][q] = 0.f;

    const int mt = wid >> 2, ng = wid & 3;
    mainloop_32x32(acc, sb, mt, ng, lane);

    // epilogue: bias + relu -> C
    const float* bp = (const float*)(sm + OFF_BIAS);
#pragma unroll
    for (int at = 0; at < 2; at++) {
        const int r0 = R0 + mt * 32 + at * 16 + (lane >> 2), r1 = r0 + 8;
#pragma unroll
        for (int j = 0; j < 4; j++) {
            const int col = ng * 32 + (j >> 1) * 16 + (j & 1) * 8 + (lane & 3) * 2;
            const float2 bb = *(const float2*)(bp + col);
            if (r0 < n) {
                float2 o = make_float2(fmaxf(acc[at][j][0] + bb.x, 0.f),
                                       fmaxf(acc[at][j][1] + bb.y, 0.f));
                *(float2*)(C + (size_t)r0 * DIM + col) = o;
            }
            if (r1 < n) {
                float2 o = make_float2(fmaxf(acc[at][j][2] + bb.x, 0.f),
                                       fmaxf(acc[at][j][3] + bb.y, 0.f));
                *(float2*)(C + (size_t)r1 * DIM + col) = o;
            }
        }
    }
}

// ---------------------------------------------------------------------------
// Scatter: one warp per edge. agg[row] += h[col] (vectorized RED), deg[row]+=1
// ---------------------------------------------------------------------------
__global__ __launch_bounds__(256) void scatter_kernel(
    const int* __restrict__ ei, int n_edges)
{
    int e    = blockIdx.x * 8 + (threadIdx.x >> 5);
    int lane = threadIdx.x & 31;
    if (e >= n_edges) return;
    int r = ei[e];
    int c = ei[n_edges + e];

    const float4 v = *(const float4*)(g_h + (size_t)c * DIM + lane * 4);
    float* dst = g_agg + (size_t)r * DIM + lane * 4;
    asm volatile("red.global.add.v4.f32 [%0], {%1,%2,%3,%4};"
                 :: "l"(dst), "f"(v.x), "f"(v.y), "f"(v.z), "f"(v.w)
                 : "memory");
    if (lane == 0)
        asm volatile("red.global.add.f32 [%0], %1;"
                     :: "l"(g_deg + r), "f"(1.0f) : "memory");
}

// ---------------------------------------------------------------------------
// GEMM1 + classifier: a = h + agg/max(deg,1); h2 = relu(a@W1^T+b1);
// out = h2@Wc^T+bc. Warps 2m x 4n; classifier partials reduced in-warp
// (4-lane shfl) then across the 4 n-quarter warps via smem.
// ---------------------------------------------------------------------------
__global__ __launch_bounds__(256, 2) void gemm1_mma(
    const float* __restrict__ W1, const float* __restrict__ b1,
    const float* __restrict__ Wc, const float* __restrict__ bc,
    float* __restrict__ out, int n)
{
    extern __shared__ char sm[];
    const u32 sb = smem_u32(sm);
    const int tid = threadIdx.x, wid = tid >> 5, lane = tid & 31;
    const int R0 = blockIdx.x * 64;

    if (tid < 128) ((float*)(sm + OFF_BIAS))[tid] = b1[tid];
    ((float*)(sm + OFF_WC))[tid]       = Wc[tid];
    ((float*)(sm + OFF_WC))[tid + 256] = Wc[tid + 256];
    if (tid < 4) ((float*)(sm + OFF_BC))[tid] = bc[tid];
    if (tid < 64) {
        const int r = R0 + tid;
        ((float*)(sm + OFF_INVD))[tid] =
            (r < n) ? (1.0f / fmaxf(g_deg[r], 1.0f)) : 0.f;
    }
    __syncthreads();   // invd visible before A staging reads it
    const float* invd_s = (const float*)(sm + OFF_INVD);

    // stage A = h + agg*invd (64x128, split bf16)
#pragma unroll
    for (int s = 0; s < 4; s++) {
        const int chunk = tid + s * 256;
        const int row = chunk >> 4, c8 = (chunk & 15) << 3;
        const u32 sw = tile_off(row, c8);
        float v[8];
        const int gr = R0 + row;
        if (gr < n) {
            const float id = invd_s[row];
            float4 h0 = *(const float4*)(g_h   + (size_t)gr * DIM + c8);
            float4 h1 = *(const float4*)(g_h   + (size_t)gr * DIM + c8 + 4);
            float4 g0 = *(const float4*)(g_agg + (size_t)gr * DIM + c8);
            float4 g1 = *(const float4*)(g_agg + (size_t)gr * DIM + c8 + 4);
            v[0]=fmaf(g0.x,id,h0.x); v[1]=fmaf(g0.y,id,h0.y);
            v[2]=fmaf(g0.z,id,h0.z); v[3]=fmaf(g0.w,id,h0.w);
            v[4]=fmaf(g1.x,id,h1.x); v[5]=fmaf(g1.y,id,h1.y);
            v[6]=fmaf(g1.z,id,h1.z); v[7]=fmaf(g1.w,id,h1.w);
        } else {
#pragma unroll
            for (int j = 0; j < 8; j++) v[j] = 0.f;
        }
        split_store(sm, OFF_AH, OFF_AL, sw, v);
    }
    stage_B(sm, W1, tid);
    __syncthreads();

    float acc[2][4][4];
#pragma unroll
    for (int at = 0; at < 2; at++)
#pragma unroll
        for (int j = 0; j < 4; j++)
#pragma unroll
            for (int q = 0; q < 4; q++) acc[at][j][q] = 0.f;

    const int mt = wid >> 2, ng = wid & 3;
    mainloop_32x32(acc, sb, mt, ng, lane);

    // epilogue: bias + relu + classifier partials over this thread's 8 cols
    const float* bp  = (const float*)(sm + OFF_BIAS);
    const float* wcs = (const float*)(sm + OFF_WC);
    float p[2][2][4];   // [at][row-half][class]
#pragma unroll
    for (int at = 0; at < 2; at++)
#pragma unroll
        for (int hh = 0; hh < 2; hh++)
#pragma unroll
            for (int c = 0; c < 4; c++) p[at][hh][c] = 0.f;

#pragma unroll
    for (int at = 0; at < 2; at++)
#pragma unroll
        for (int j = 0; j < 4; j++) {
            const int col = ng * 32 + (j >> 1) * 16 + (j & 1) * 8 + (lane & 3) * 2;
            const float2 bb = *(const float2*)(bp + col);
            const float ha = fmaxf(acc[at][j][0] + bb.x, 0.f);
            const float hb = fmaxf(acc[at][j][1] + bb.y, 0.f);
            const float hc = fmaxf(acc[at][j][2] + bb.x, 0.f);
            const float hd = fmaxf(acc[at][j][3] + bb.y, 0.f);
#pragma unroll
            for (int c = 0; c < 4; c++) {
                const float2 w = *(const float2*)(wcs + c * 128 + col);
                p[at][0][c] = fmaf(ha, w.x, fmaf(hb, w.y, p[at][0][c]));
                p[at][1][c] = fmaf(hc, w.x, fmaf(hd, w.y, p[at][1][c]));
            }
        }
    // reduce over the 4 lanes sharing each row
#pragma unroll
    for (int d = 1; d < 4; d <<= 1)
#pragma unroll
        for (int at = 0; at < 2; at++)
#pragma unroll
            for (int hh = 0; hh < 2; hh++)
#pragma unroll
                for (int c = 0; c < 4; c++)
                    p[at][hh][c] += __shfl_xor_sync(0xffffffffu, p[at][hh][c], d);

    // cross-warp (n-quarter) combine via smem: cpart[ng][row_local][class]
    float* cpart = (float*)(sm + OFF_CP);
    if ((lane & 3) == 0) {
#pragma unroll
        for (int at = 0; at < 2; at++) {
            const int rl = mt * 32 + at * 16 + (lane >> 2);
#pragma unroll
            for (int c = 0; c < 4; c++) {
                cpart[(ng * 64 + rl) * 4 + c]     = p[at][0][c];
                cpart[(ng * 64 + rl + 8) * 4 + c] = p[at][1][c];
            }
        }
    }
    __syncthreads();
    {
        const int rl = tid >> 2, c = tid & 3;   // 64 rows x 4 classes
        const int r = R0 + rl;
        if (r < n) {
            const float* bcp = (const float*)(sm + OFF_BC);
            out[(size_t)r * 4 + c] =
                ((cpart[rl * 4 + c] + cpart[(64 + rl) * 4 + c]) +
                 (cpart[(128 + rl) * 4 + c] + cpart[(192 + rl) * 4 + c])) + bcp[c];
        }
    }
}

// ---------------------------------------------------------------------------
extern "C" void kernel_launch(void* const* d_in, const int* in_sizes, int n_in,
                              void* d_out, int out_size)
{
    const float* x  = (const float*)d_in[0];
    const int*   ei = (const int*)  d_in[1];
    const float* W0 = (const float*)d_in[2];
    const float* b0 = (const float*)d_in[3];
    const float* W1 = (const float*)d_in[4];
    const float* b1 = (const float*)d_in[5];
    const float* Wc = (const float*)d_in[6];
    const float* bc = (const float*)d_in[7];
    float* out = (float*)d_out;

    const int n       = in_sizes[0] / DIM;
    const int n_edges = in_sizes[1] / 2;

    void *degp, *hp;
    cudaGetSymbolAddress(&degp, g_deg);
    cudaGetSymbolAddress(&hp,   g_h);

    cudaFuncSetAttribute(gemm0_mma, cudaFuncAttributeMaxDynamicSharedMemorySize, SMEM_BYTES);
    cudaFuncSetAttribute(gemm1_mma, cudaFuncAttributeMaxDynamicSharedMemorySize, SMEM_BYTES);

    cudaMemsetAsync(degp, 0, (size_t)n * sizeof(float));   // agg zeroed inside gemm0

    const int gblocks = (n + 63) / 64;
    gemm0_mma<<<gblocks, 256, SMEM_BYTES>>>(x, W0, b0, (float*)hp, n);
    scatter_kernel<<<(n_edges + 7) / 8, 256>>>(ei, n_edges);
    gemm1_mma<<<gblocks, 256, SMEM_BYTES>>>(W1, b1, Wc, bc, out, n);
}

// round 14
// speedup vs baseline: 1.0362x; 1.0362x over previous
#include <cuda_runtime.h>
#include <cuda_bf16.h>
#include <cstdint>

#define NODES_MAX 100000
#define DIM 128

typedef unsigned int u32;

// Scratch (allocation-free rule: __device__ globals)
__device__ float g_h[(size_t)NODES_MAX * DIM];     // relu(x@W0^T+b0)
__device__ float g_agg[(size_t)NODES_MAX * DIM];   // scatter-add accumulator
__device__ float g_deg[NODES_MAX];                 // degree accumulator

// ---------------- smem layout (bytes) ----------------
#define OFF_BIAS 0            // 128 f32
#define OFF_WC   512          // 512 f32
#define OFF_BC   2560         // 4 f32
#define OFF_INVD 2576         // 64 f32
#define OFF_CP   4096         // 2KB classifier cross-warp partials
#define OFF_AH   8192         // 16KB (64x128 bf16)
#define OFF_AL   24576        // 16KB
#define OFF_BH   40960        // 32KB (128x128 bf16)
#define OFF_BL   73728        // 32KB
#define SMEM_BYTES 106496

// ---------------- helpers ----------------
__device__ __forceinline__ u32 smem_u32(const void* p) {
    u32 a;
    asm("{ .reg .u64 t; cvta.to.shared.u64 t, %1; cvt.u32.u64 %0, t; }" : "=r"(a) : "l"(p));
    return a;
}

__device__ __forceinline__ void ldsm_x4(u32* r, u32 addr) {
    asm volatile("ldmatrix.sync.aligned.m8n8.x4.shared.b16 {%0,%1,%2,%3}, [%4];"
                 : "=r"(r[0]), "=r"(r[1]), "=r"(r[2]), "=r"(r[3]) : "r"(addr));
}

__device__ __forceinline__ void mma_bf16(float* d, const u32* a, u32 b0, u32 b1) {
    asm volatile(
        "mma.sync.aligned.m16n8k16.row.col.f32.bf16.bf16.f32 "
        "{%0,%1,%2,%3}, {%4,%5,%6,%7}, {%8,%9}, {%0,%1,%2,%3};"
        : "+f"(d[0]), "+f"(d[1]), "+f"(d[2]), "+f"(d[3])
        : "r"(a[0]), "r"(a[1]), "r"(a[2]), "r"(a[3]), "r"(b0), "r"(b1));
}

// byte offset of 16B chunk (row, c8) in a 256B-pitch tile, XOR-8 swizzle
__device__ __forceinline__ u32 tile_off(int row, int c8) {
    return (u32)(row * 256 + (((c8 >> 3) ^ (row & 7)) << 4));
}

// hi/lo bf16 split of 8 floats -> one 16B store into each of two tiles
__device__ __forceinline__ void split_store(char* smb, int hi_off, int lo_off,
                                            u32 sw, const float* v) {
    u32 h[4], l[4];
#pragma unroll
    for (int j = 0; j < 4; j++) {
        float2 f = make_float2(v[2*j], v[2*j+1]);
        __nv_bfloat162 hb = __float22bfloat162_rn(f);
        float2 hf = __bfloat1622float2(hb);
        float2 r = make_float2(f.x - hf.x, f.y - hf.y);
        __nv_bfloat162 lb = __float22bfloat162_rn(r);
        h[j] = *(u32*)&hb;
        l[j] = *(u32*)&lb;
    }
    *(uint4*)(smb + hi_off + sw) = make_uint4(h[0], h[1], h[2], h[3]);
    *(uint4*)(smb + lo_off + sw) = make_uint4(l[0], l[1], l[2], l[3]);
}

// stage B = W (128x128, split bf16), 256 threads
__device__ __forceinline__ void stage_B(char* sm, const float* __restrict__ W, int tid) {
#pragma unroll
    for (int s = 0; s < 8; s++) {
        const int chunk = tid + s * 256;
        const int row = chunk >> 4, c8 = (chunk & 15) << 3;
        const u32 sw = tile_off(row, c8);
        float w[8];
        float4 w0 = *(const float4*)(W + row * DIM + c8);
        float4 w1 = *(const float4*)(W + row * DIM + c8 + 4);
        w[0]=w0.x; w[1]=w0.y; w[2]=w0.z; w[3]=w0.w;
        w[4]=w1.x; w[5]=w1.y; w[6]=w1.z; w[7]=w1.w;
        split_store(sm, OFF_BH, OFF_BL, sw, w);
    }
}

// mainloop: warp tile 16m x 64n, phase-reordered MMAs.
// Per b-pair: 4x AhBh, then 4x AhBl, then 4x AlBh -> dependent MMAs on the
// same accumulator are 4 apart (covers HMMA latency; asm volatile keeps order).
__device__ __forceinline__ void mainloop_16x64(float acc[8][4], u32 sb,
                                               int mt, int nh, int lane) {
    const int a_row  = mt * 16 + (lane & 15);
    const int a_sel  = lane >> 4;
    const int b_rowl = (lane & 7) + ((lane >> 4) << 3);
    const int b_sel  = (lane >> 3) & 1;
    const int n0     = nh * 64;
    const u32 a_hi = sb + OFF_AH + a_row * 256;
    const u32 a_lo = sb + OFF_AL + a_row * 256;

    u32 aH[4], aL[4], bH[2][4], bL[2][4];
#pragma unroll
    for (int kk = 0; kk < 8; kk++) {
        const u32 ao = (u32)(((2 * kk + a_sel) ^ (a_row & 7)) << 4);
        ldsm_x4(aH, a_hi + ao);
        ldsm_x4(aL, a_lo + ao);
        const u32 bo = (u32)(((2 * kk + b_sel) ^ (b_rowl & 7)) << 4);
#pragma unroll
        for (int half = 0; half < 2; half++) {
#pragma unroll
            for (int t = 0; t < 2; t++) {
                const int g = half * 2 + t;
                const u32 brow = (u32)((n0 + g * 16 + b_rowl) * 256);
                ldsm_x4(bH[t], sb + OFF_BH + brow + bo);
                ldsm_x4(bL[t], sb + OFF_BL + brow + bo);
            }
            float* a0 = acc[half * 4 + 0];
            float* a1 = acc[half * 4 + 1];
            float* a2 = acc[half * 4 + 2];
            float* a3 = acc[half * 4 + 3];
            // phase 1: Ah*Bh (4 independent)
            mma_bf16(a0, aH, bH[0][0], bH[0][1]);
            mma_bf16(a1, aH, bH[0][2], bH[0][3]);
            mma_bf16(a2, aH, bH[1][0], bH[1][1]);
            mma_bf16(a3, aH, bH[1][2], bH[1][3]);
            // phase 2: Ah*Bl
            mma_bf16(a0, aH, bL[0][0], bL[0][1]);
            mma_bf16(a1, aH, bL[0][2], bL[0][3]);
            mma_bf16(a2, aH, bL[1][0], bL[1][1]);
            mma_bf16(a3, aH, bL[1][2], bL[1][3]);
            // phase 3: Al*Bh
            mma_bf16(a0, aL, bH[0][0], bH[0][1]);
            mma_bf16(a1, aL, bH[0][2], bH[0][3]);
            mma_bf16(a2, aL, bH[1][0], bH[1][1]);
            mma_bf16(a3, aL, bH[1][2], bH[1][3]);
        }
    }
}

// ---------------------------------------------------------------------------
// GEMM0: h = relu(x @ W0^T + b0). CTA 64x128, 256 threads, 8 warps 16m x 64n.
// ---------------------------------------------------------------------------
__global__ __launch_bounds__(256, 2) void gemm0_mma(
    const float* __restrict__ A, const float* __restrict__ W,
    const float* __restrict__ bias, float* __restrict__ C, int n)
{
    extern __shared__ char sm[];
    const u32 sb = smem_u32(sm);
    const int tid = threadIdx.x, wid = tid >> 5, lane = tid & 31;
    const int R0 = blockIdx.x * 64;

    if (tid < 128) ((float*)(sm + OFF_BIAS))[tid] = bias[tid];

    // stage A (64x128, split bf16)
#pragma unroll
    for (int s = 0; s < 4; s++) {
        const int chunk = tid + s * 256;
        const int row = chunk >> 4, c8 = (chunk & 15) << 3;
        const u32 sw = tile_off(row, c8);
        float v[8];
        const int gr = R0 + row;
        if (gr < n) {
            float4 a0 = *(const float4*)(A + (size_t)gr * DIM + c8);
            float4 a1 = *(const float4*)(A + (size_t)gr * DIM + c8 + 4);
            v[0]=a0.x; v[1]=a0.y; v[2]=a0.z; v[3]=a0.w;
            v[4]=a1.x; v[5]=a1.y; v[6]=a1.z; v[7]=a1.w;
        } else {
#pragma unroll
            for (int j = 0; j < 8; j++) v[j] = 0.f;
        }
        split_store(sm, OFF_AH, OFF_AL, sw, v);
    }
    stage_B(sm, W, tid);
    __syncthreads();

    float acc[8][4];
#pragma unroll
    for (int j = 0; j < 8; j++)
#pragma unroll
        for (int q = 0; q < 4; q++) acc[j][q] = 0.f;

    const int mt = wid >> 1, nh = wid & 1;
    mainloop_16x64(acc, sb, mt, nh, lane);

    // epilogue: bias + relu -> C
    const int n0 = nh * 64;
    const int r0 = R0 + mt * 16 + (lane >> 2), r1 = r0 + 8;
    const float* bp = (const float*)(sm + OFF_BIAS);
#pragma unroll
    for (int j = 0; j < 8; j++) {
        const int col = n0 + j * 8 + (lane & 3) * 2;
        const float2 bb = *(const float2*)(bp + col);
        if (r0 < n) {
            float2 o = make_float2(fmaxf(acc[j][0] + bb.x, 0.f),
                                   fmaxf(acc[j][1] + bb.y, 0.f));
            *(float2*)(C + (size_t)r0 * DIM + col) = o;
        }
        if (r1 < n) {
            float2 o = make_float2(fmaxf(acc[j][2] + bb.x, 0.f),
                                   fmaxf(acc[j][3] + bb.y, 0.f));
            *(float2*)(C + (size_t)r1 * DIM + col) = o;
        }
    }
}

// ---------------------------------------------------------------------------
// Scatter: one warp per edge. agg[row] += h[col] (vectorized RED), deg[row]+=1
// ---------------------------------------------------------------------------
__global__ __launch_bounds__(256) void scatter_kernel(
    const int* __restrict__ ei, int n_edges)
{
    int e    = blockIdx.x * 8 + (threadIdx.x >> 5);
    int lane = threadIdx.x & 31;
    if (e >= n_edges) return;
    int r = ei[e];
    int c = ei[n_edges + e];

    const float4 v = *(const float4*)(g_h + (size_t)c * DIM + lane * 4);
    float* dst = g_agg + (size_t)r * DIM + lane * 4;
    asm volatile("red.global.add.v4.f32 [%0], {%1,%2,%3,%4};"
                 :: "l"(dst), "f"(v.x), "f"(v.y), "f"(v.z), "f"(v.w)
                 : "memory");
    if (lane == 0)
        asm volatile("red.global.add.f32 [%0], %1;"
                     :: "l"(g_deg + r), "f"(1.0f) : "memory");
}

// ---------------------------------------------------------------------------
// GEMM1 + classifier: a = h + agg/max(deg,1); h2 = relu(a@W1^T+b1);
// out = h2@Wc^T+bc. 256 threads; classifier partials reduced in-warp (4-lane
// shfl) then across the two n-half warps via a small smem buffer.
// ---------------------------------------------------------------------------
__global__ __launch_bounds__(256, 2) void gemm1_mma(
    const float* __restrict__ W1, const float* __restrict__ b1,
    const float* __restrict__ Wc, const float* __restrict__ bc,
    float* __restrict__ out, int n)
{
    extern __shared__ char sm[];
    const u32 sb = smem_u32(sm);
    const int tid = threadIdx.x, wid = tid >> 5, lane = tid & 31;
    const int R0 = blockIdx.x * 64;

    if (tid < 128) ((float*)(sm + OFF_BIAS))[tid] = b1[tid];
    ((float*)(sm + OFF_WC))[tid]       = Wc[tid];
    ((float*)(sm + OFF_WC))[tid + 256] = Wc[tid + 256];
    if (tid < 4) ((float*)(sm + OFF_BC))[tid] = bc[tid];
    if (tid < 64) {
        const int r = R0 + tid;
        ((float*)(sm + OFF_INVD))[tid] =
            (r < n) ? (1.0f / fmaxf(g_deg[r], 1.0f)) : 0.f;
    }
    __syncthreads();   // invd visible before A staging reads it
    const float* invd_s = (const float*)(sm + OFF_INVD);

    // stage A = h + agg*invd (64x128, split bf16)
#pragma unroll
    for (int s = 0; s < 4; s++) {
        const int chunk = tid + s * 256;
        const int row = chunk >> 4, c8 = (chunk & 15) << 3;
        const u32 sw = tile_off(row, c8);
        float v[8];
        const int gr = R0 + row;
        if (gr < n) {
            const float id = invd_s[row];
            float4 h0 = *(const float4*)(g_h   + (size_t)gr * DIM + c8);
            float4 h1 = *(const float4*)(g_h   + (size_t)gr * DIM + c8 + 4);
            float4 g0 = *(const float4*)(g_agg + (size_t)gr * DIM + c8);
            float4 g1 = *(const float4*)(g_agg + (size_t)gr * DIM + c8 + 4);
            v[0]=fmaf(g0.x,id,h0.x); v[1]=fmaf(g0.y,id,h0.y);
            v[2]=fmaf(g0.z,id,h0.z); v[3]=fmaf(g0.w,id,h0.w);
            v[4]=fmaf(g1.x,id,h1.x); v[5]=fmaf(g1.y,id,h1.y);
            v[6]=fmaf(g1.z,id,h1.z); v[7]=fmaf(g1.w,id,h1.w);
        } else {
#pragma unroll
            for (int j = 0; j < 8; j++) v[j] = 0.f;
        }
        split_store(sm, OFF_AH, OFF_AL, sw, v);
    }
    stage_B(sm, W1, tid);
    __syncthreads();

    float acc[8][4];
#pragma unroll
    for (int j = 0; j < 8; j++)
#pragma unroll
        for (int q = 0; q < 4; q++) acc[j][q] = 0.f;

    const int mt = wid >> 1, nh = wid & 1;
    mainloop_16x64(acc, sb, mt, nh, lane);

    // epilogue: bias + relu + classifier partials over this thread's cols
    const int n0 = nh * 64;
    const float* bp  = (const float*)(sm + OFF_BIAS);
    const float* wcs = (const float*)(sm + OFF_WC);
    float p0[4] = {0.f, 0.f, 0.f, 0.f};
    float p1[4] = {0.f, 0.f, 0.f, 0.f};
#pragma unroll
    for (int j = 0; j < 8; j++) {
        const int col = n0 + j * 8 + (lane & 3) * 2;
        const float2 bb = *(const float2*)(bp + col);
        const float ha = fmaxf(acc[j][0] + bb.x, 0.f);
        const float hb = fmaxf(acc[j][1] + bb.y, 0.f);
        const float hc = fmaxf(acc[j][2] + bb.x, 0.f);
        const float hd = fmaxf(acc[j][3] + bb.y, 0.f);
#pragma unroll
        for (int c = 0; c < 4; c++) {
            const float2 w = *(const float2*)(wcs + c * 128 + col);
            p0[c] = fmaf(ha, w.x, fmaf(hb, w.y, p0[c]));
            p1[c] = fmaf(hc, w.x, fmaf(hd, w.y, p1[c]));
        }
    }
    // reduce over the 4 lanes sharing a row
#pragma unroll
    for (int d = 1; d < 4; d <<= 1)
#pragma unroll
        for (int c = 0; c < 4; c++) {
            p0[c] += __shfl_xor_sync(0xffffffffu, p0[c], d);
            p1[c] += __shfl_xor_sync(0xffffffffu, p1[c], d);
        }

    // cross-warp (n-half) combine via smem: cpart[nh][row_local][class]
    float* cpart = (float*)(sm + OFF_CP);
    if ((lane & 3) == 0) {
        const int rl0 = mt * 16 + (lane >> 2), rl1 = rl0 + 8;
#pragma unroll
        for (int c = 0; c < 4; c++) {
            cpart[(nh * 64 + rl0) * 4 + c] = p0[c];
            cpart[(nh * 64 + rl1) * 4 + c] = p1[c];
        }
    }
    __syncthreads();
    {
        const int rl = tid >> 2, c = tid & 3;   // 64 rows x 4 classes
        const int r = R0 + rl;
        if (r < n) {
            const float* bcp = (const float*)(sm + OFF_BC);
            out[(size_t)r * 4 + c] =
                cpart[rl * 4 + c] + cpart[(64 + rl) * 4 + c] + bcp[c];
        }
    }
}

// ---------------------------------------------------------------------------
extern "C" void kernel_launch(void* const* d_in, const int* in_sizes, int n_in,
                              void* d_out, int out_size)
{
    const float* x  = (const float*)d_in[0];
    const int*   ei = (const int*)  d_in[1];
    const float* W0 = (const float*)d_in[2];
    const float* b0 = (const float*)d_in[3];
    const float* W1 = (const float*)d_in[4];
    const float* b1 = (const float*)d_in[5];
    const float* Wc = (const float*)d_in[6];
    const float* bc = (const float*)d_in[7];
    float* out = (float*)d_out;

    const int n       = in_sizes[0] / DIM;
    const int n_edges = in_sizes[1] / 2;

    void *aggp, *degp, *hp;
    cudaGetSymbolAddress(&aggp, g_agg);
    cudaGetSymbolAddress(&degp, g_deg);
    cudaGetSymbolAddress(&hp,   g_h);

    cudaFuncSetAttribute(gemm0_mma, cudaFuncAttributeMaxDynamicSharedMemorySize, SMEM_BYTES);
    cudaFuncSetAttribute(gemm1_mma, cudaFuncAttributeMaxDynamicSharedMemorySize, SMEM_BYTES);

    cudaMemsetAsync(aggp, 0, (size_t)n * DIM * sizeof(float));
    cudaMemsetAsync(degp, 0, (size_t)n * sizeof(float));

    const int gblocks = (n + 63) / 64;
    gemm0_mma<<<gblocks, 256, SMEM_BYTES>>>(x, W0, b0, (float*)hp, n);
    scatter_kernel<<<(n_edges + 7) / 8, 256>>>(ei, n_edges);
    gemm1_mma<<<gblocks, 256, SMEM_BYTES>>>(W1, b1, Wc, bc, out, n);
}

// round 15
// speedup vs baseline: 1.0475x; 1.0110x over previous
#include <cuda_runtime.h>
#include <cuda_bf16.h>
#include <cstdint>

#define NODES_MAX 100000
#define DIM 128

typedef unsigned int u32;

// Scratch (allocation-free rule: __device__ globals)
__device__ float g_h[(size_t)NODES_MAX * DIM];     // relu(x@W0^T+b0)
__device__ float g_agg[(size_t)NODES_MAX * DIM];   // scatter-add accumulator
__device__ float g_deg[NODES_MAX];                 // degree accumulator

// ---------------- smem layout (bytes) ----------------
#define OFF_BIAS 0            // 128 f32
#define OFF_WC   512          // 512 f32
#define OFF_BC   2560         // 4 f32
#define OFF_INVD 2576         // 64 f32
#define OFF_CP   4096         // 4KB classifier cross-warp partials (4 ng x 64 x 4)
#define OFF_AH   8192         // 16KB (64x128 bf16)
#define OFF_AL   24576        // 16KB
#define OFF_BH   40960        // 32KB (128x128 bf16)
#define OFF_BL   73728        // 32KB
#define SMEM_BYTES 106496

// ---------------- helpers ----------------
__device__ __forceinline__ u32 smem_u32(const void* p) {
    u32 a;
    asm("{ .reg .u64 t; cvta.to.shared.u64 t, %1; cvt.u32.u64 %0, t; }" : "=r"(a) : "l"(p));
    return a;
}

__device__ __forceinline__ void ldsm_x4(u32* r, u32 addr) {
    asm volatile("ldmatrix.sync.aligned.m8n8.x4.shared.b16 {%0,%1,%2,%3}, [%4];"
                 : "=r"(r[0]), "=r"(r[1]), "=r"(r[2]), "=r"(r[3]) : "r"(addr));
}

__device__ __forceinline__ void mma_bf16(float* d, const u32* a, u32 b0, u32 b1) {
    asm volatile(
        "mma.sync.aligned.m16n8k16.row.col.f32.bf16.bf16.f32 "
        "{%0,%1,%2,%3}, {%4,%5,%6,%7}, {%8,%9}, {%0,%1,%2,%3};"
        : "+f"(d[0]), "+f"(d[1]), "+f"(d[2]), "+f"(d[3])
        : "r"(a[0]), "r"(a[1]), "r"(a[2]), "r"(a[3]), "r"(b0), "r"(b1));
}

// byte offset of 16B chunk (row, c8) in a 256B-pitch tile, XOR-8 swizzle
__device__ __forceinline__ u32 tile_off(int row, int c8) {
    return (u32)(row * 256 + (((c8 >> 3) ^ (row & 7)) << 4));
}

// hi/lo bf16 split of 8 floats -> one 16B store into each of two tiles
__device__ __forceinline__ void split_store(char* smb, int hi_off, int lo_off,
                                            u32 sw, const float* v) {
    u32 h[4], l[4];
#pragma unroll
    for (int j = 0; j < 4; j++) {
        float2 f = make_float2(v[2*j], v[2*j+1]);
        __nv_bfloat162 hb = __float22bfloat162_rn(f);
        float2 hf = __bfloat1622float2(hb);
        float2 r = make_float2(f.x - hf.x, f.y - hf.y);
        __nv_bfloat162 lb = __float22bfloat162_rn(r);
        h[j] = *(u32*)&hb;
        l[j] = *(u32*)&lb;
    }
    *(uint4*)(smb + hi_off + sw) = make_uint4(h[0], h[1], h[2], h[3]);
    *(uint4*)(smb + lo_off + sw) = make_uint4(l[0], l[1], l[2], l[3]);
}

// stage B = W (128x128, split bf16), 256 threads
__device__ __forceinline__ void stage_B(char* sm, const float* __restrict__ W, int tid) {
#pragma unroll
    for (int s = 0; s < 8; s++) {
        const int chunk = tid + s * 256;
        const int row = chunk >> 4, c8 = (chunk & 15) << 3;
        const u32 sw = tile_off(row, c8);
        float w[8];
        float4 w0 = *(const float4*)(W + row * DIM + c8);
        float4 w1 = *(const float4*)(W + row * DIM + c8 + 4);
        w[0]=w0.x; w[1]=w0.y; w[2]=w0.z; w[3]=w0.w;
        w[4]=w1.x; w[5]=w1.y; w[6]=w1.z; w[7]=w1.w;
        split_store(sm, OFF_BH, OFF_BL, sw, w);
    }
}

// mainloop: warp tile 32m x 32n. mt = m-half (0..1), ng = n-quarter (0..3).
// Per kk per warp: 4 a-LDSM + 4 b-LDSM for 24 MMAs (CTA total 64 LDSM/kk,
// vs 96 for the 16x64 tile) -> smem crossbar pressure -33%.
__device__ __forceinline__ void mainloop_32x32(float acc[2][4][4], u32 sb,
                                               int mt, int ng, int lane) {
    const int l7     = lane & 7;
    const int a_sel  = lane >> 4;
    const int b_rowl = l7 + ((lane >> 4) << 3);
    const int b_sel  = (lane >> 3) & 1;
    const int arow0  = mt * 32 + (lane & 15);

    u32 aH[2][4], aL[2][4], bH[2][4], bL[2][4];
#pragma unroll
    for (int kk = 0; kk < 8; kk++) {
        const u32 ao = (u32)(((2 * kk + a_sel) ^ l7) << 4);
        const u32 bo = (u32)(((2 * kk + b_sel) ^ l7) << 4);
#pragma unroll
        for (int at = 0; at < 2; at++) {
            const u32 ar = (u32)((arow0 + at * 16) * 256);
            ldsm_x4(aH[at], sb + OFF_AH + ar + ao);
            ldsm_x4(aL[at], sb + OFF_AL + ar + ao);
        }
#pragma unroll
        for (int g = 0; g < 2; g++) {
            const u32 br = (u32)((ng * 32 + g * 16 + b_rowl) * 256);
            ldsm_x4(bH[g], sb + OFF_BH + br + bo);
            ldsm_x4(bL[g], sb + OFF_BL + br + bo);
        }
        // phase-grouped: dependent MMAs on same acc are >=4 apart
#pragma unroll
        for (int at = 0; at < 2; at++)
#pragma unroll
            for (int g = 0; g < 2; g++) {
                mma_bf16(acc[at][2*g],   aH[at], bH[g][0], bH[g][1]);
                mma_bf16(acc[at][2*g+1], aH[at], bH[g][2], bH[g][3]);
            }
#pragma unroll
        for (int at = 0; at < 2; at++)
#pragma unroll
            for (int g = 0; g < 2; g++) {
                mma_bf16(acc[at][2*g],   aH[at], bL[g][0], bL[g][1]);
                mma_bf16(acc[at][2*g+1], aH[at], bL[g][2], bL[g][3]);
            }
#pragma unroll
        for (int at = 0; at < 2; at++)
#pragma unroll
            for (int g = 0; g < 2; g++) {
                mma_bf16(acc[at][2*g],   aL[at], bH[g][0], bH[g][1]);
                mma_bf16(acc[at][2*g+1], aL[at], bH[g][2], bH[g][3]);
            }
    }
}

// ---------------------------------------------------------------------------
// GEMM0: h = relu(x @ W0^T + b0). CTA 64x128, 256 threads, warps 2m x 4n.
// ---------------------------------------------------------------------------
__global__ __launch_bounds__(256, 2) void gemm0_mma(
    const float* __restrict__ A, const float* __restrict__ W,
    const float* __restrict__ bias, float* __restrict__ C, int n)
{
    extern __shared__ char sm[];
    const u32 sb = smem_u32(sm);
    const int tid = threadIdx.x, wid = tid >> 5, lane = tid & 31;
    const int R0 = blockIdx.x * 64;

    if (tid < 128) ((float*)(sm + OFF_BIAS))[tid] = bias[tid];

    // stage A (64x128, split bf16)
#pragma unroll
    for (int s = 0; s < 4; s++) {
        const int chunk = tid + s * 256;
        const int row = chunk >> 4, c8 = (chunk & 15) << 3;
        const u32 sw = tile_off(row, c8);
        float v[8];
        const int gr = R0 + row;
        if (gr < n) {
            float4 a0 = *(const float4*)(A + (size_t)gr * DIM + c8);
            float4 a1 = *(const float4*)(A + (size_t)gr * DIM + c8 + 4);
            v[0]=a0.x; v[1]=a0.y; v[2]=a0.z; v[3]=a0.w;
            v[4]=a1.x; v[5]=a1.y; v[6]=a1.z; v[7]=a1.w;
        } else {
#pragma unroll
            for (int j = 0; j < 8; j++) v[j] = 0.f;
        }
        split_store(sm, OFF_AH, OFF_AL, sw, v);
    }
    stage_B(sm, W, tid);
    __syncthreads();

    float acc[2][4][4];
#pragma unroll
    for (int at = 0; at < 2; at++)
#pragma unroll
        for (int j = 0; j < 4; j++)
#pragma unroll
            for (int q = 0; q < 4; q++) acc[at][j][q] = 0.f;

    const int mt = wid >> 2, ng = wid & 3;
    mainloop_32x32(acc, sb, mt, ng, lane);

    // epilogue: bias + relu -> C
    const float* bp = (const float*)(sm + OFF_BIAS);
#pragma unroll
    for (int at = 0; at < 2; at++) {
        const int r0 = R0 + mt * 32 + at * 16 + (lane >> 2), r1 = r0 + 8;
#pragma unroll
        for (int j = 0; j < 4; j++) {
            const int col = ng * 32 + (j >> 1) * 16 + (j & 1) * 8 + (lane & 3) * 2;
            const float2 bb = *(const float2*)(bp + col);
            if (r0 < n) {
                float2 o = make_float2(fmaxf(acc[at][j][0] + bb.x, 0.f),
                                       fmaxf(acc[at][j][1] + bb.y, 0.f));
                *(float2*)(C + (size_t)r0 * DIM + col) = o;
            }
            if (r1 < n) {
                float2 o = make_float2(fmaxf(acc[at][j][2] + bb.x, 0.f),
                                       fmaxf(acc[at][j][3] + bb.y, 0.f));
                *(float2*)(C + (size_t)r1 * DIM + col) = o;
            }
        }
    }
}

// ---------------------------------------------------------------------------
// Scatter: one warp per edge. agg[row] += h[col] (vectorized RED), deg[row]+=1
// ---------------------------------------------------------------------------
__global__ __launch_bounds__(256) void scatter_kernel(
    const int* __restrict__ ei, int n_edges)
{
    int e    = blockIdx.x * 8 + (threadIdx.x >> 5);
    int lane = threadIdx.x & 31;
    if (e >= n_edges) return;
    int r = ei[e];
    int c = ei[n_edges + e];

    const float4 v = *(const float4*)(g_h + (size_t)c * DIM + lane * 4);
    float* dst = g_agg + (size_t)r * DIM + lane * 4;
    asm volatile("red.global.add.v4.f32 [%0], {%1,%2,%3,%4};"
                 :: "l"(dst), "f"(v.x), "f"(v.y), "f"(v.z), "f"(v.w)
                 : "memory");
    if (lane == 0)
        asm volatile("red.global.add.f32 [%0], %1;"
                     :: "l"(g_deg + r), "f"(1.0f) : "memory");
}

// ---------------------------------------------------------------------------
// GEMM1 + classifier: a = h + agg/max(deg,1); h2 = relu(a@W1^T+b1);
// out = h2@Wc^T+bc. Warps 2m x 4n; classifier partials reduced in-warp
// (4-lane shfl) then across the 4 n-quarter warps via smem.
// ---------------------------------------------------------------------------
__global__ __launch_bounds__(256, 2) void gemm1_mma(
    const float* __restrict__ W1, const float* __restrict__ b1,
    const float* __restrict__ Wc, const float* __restrict__ bc,
    float* __restrict__ out, int n)
{
    extern __shared__ char sm[];
    const u32 sb = smem_u32(sm);
    const int tid = threadIdx.x, wid = tid >> 5, lane = tid & 31;
    const int R0 = blockIdx.x * 64;

    if (tid < 128) ((float*)(sm + OFF_BIAS))[tid] = b1[tid];
    ((float*)(sm + OFF_WC))[tid]       = Wc[tid];
    ((float*)(sm + OFF_WC))[tid + 256] = Wc[tid + 256];
    if (tid < 4) ((float*)(sm + OFF_BC))[tid] = bc[tid];
    if (tid < 64) {
        const int r = R0 + tid;
        ((float*)(sm + OFF_INVD))[tid] =
            (r < n) ? (1.0f / fmaxf(g_deg[r], 1.0f)) : 0.f;
    }
    __syncthreads();   // invd visible before A staging reads it
    const float* invd_s = (const float*)(sm + OFF_INVD);

    // stage A = h + agg*invd (64x128, split bf16)
#pragma unroll
    for (int s = 0; s < 4; s++) {
        const int chunk = tid + s * 256;
        const int row = chunk >> 4, c8 = (chunk & 15) << 3;
        const u32 sw = tile_off(row, c8);
        float v[8];
        const int gr = R0 + row;
        if (gr < n) {
            const float id = invd_s[row];
            float4 h0 = *(const float4*)(g_h   + (size_t)gr * DIM + c8);
            float4 h1 = *(const float4*)(g_h   + (size_t)gr * DIM + c8 + 4);
            float4 g0 = *(const float4*)(g_agg + (size_t)gr * DIM + c8);
            float4 g1 = *(const float4*)(g_agg + (size_t)gr * DIM + c8 + 4);
            v[0]=fmaf(g0.x,id,h0.x); v[1]=fmaf(g0.y,id,h0.y);
            v[2]=fmaf(g0.z,id,h0.z); v[3]=fmaf(g0.w,id,h0.w);
            v[4]=fmaf(g1.x,id,h1.x); v[5]=fmaf(g1.y,id,h1.y);
            v[6]=fmaf(g1.z,id,h1.z); v[7]=fmaf(g1.w,id,h1.w);
        } else {
#pragma unroll
            for (int j = 0; j < 8; j++) v[j] = 0.f;
        }
        split_store(sm, OFF_AH, OFF_AL, sw, v);
    }
    stage_B(sm, W1, tid);
    __syncthreads();

    float acc[2][4][4];
#pragma unroll
    for (int at = 0; at < 2; at++)
#pragma unroll
        for (int j = 0; j < 4; j++)
#pragma unroll
            for (int q = 0; q < 4; q++) acc[at][j][q] = 0.f;

    const int mt = wid >> 2, ng = wid & 3;
    mainloop_32x32(acc, sb, mt, ng, lane);

    // epilogue: bias + relu + classifier partials over this thread's 8 cols
    const float* bp  = (const float*)(sm + OFF_BIAS);
    const float* wcs = (const float*)(sm + OFF_WC);
    float p[2][2][4];   // [at][row-half][class]
#pragma unroll
    for (int at = 0; at < 2; at++)
#pragma unroll
        for (int hh = 0; hh < 2; hh++)
#pragma unroll
            for (int c = 0; c < 4; c++) p[at][hh][c] = 0.f;

#pragma unroll
    for (int at = 0; at < 2; at++)
#pragma unroll
        for (int j = 0; j < 4; j++) {
            const int col = ng * 32 + (j >> 1) * 16 + (j & 1) * 8 + (lane & 3) * 2;
            const float2 bb = *(const float2*)(bp + col);
            const float ha = fmaxf(acc[at][j][0] + bb.x, 0.f);
            const float hb = fmaxf(acc[at][j][1] + bb.y, 0.f);
            const float hc = fmaxf(acc[at][j][2] + bb.x, 0.f);
            const float hd = fmaxf(acc[at][j][3] + bb.y, 0.f);
#pragma unroll
            for (int c = 0; c < 4; c++) {
                const float2 w = *(const float2*)(wcs + c * 128 + col);
                p[at][0][c] = fmaf(ha, w.x, fmaf(hb, w.y, p[at][0][c]));
                p[at][1][c] = fmaf(hc, w.x, fmaf(hd, w.y, p[at][1][c]));
            }
        }
    // reduce over the 4 lanes sharing each row
#pragma unroll
    for (int d = 1; d < 4; d <<= 1)
#pragma unroll
        for (int at = 0; at < 2; at++)
#pragma unroll
            for (int hh = 0; hh < 2; hh++)
#pragma unroll
                for (int c = 0; c < 4; c++)
                    p[at][hh][c] += __shfl_xor_sync(0xffffffffu, p[at][hh][c], d);

    // cross-warp (n-quarter) combine via smem: cpart[ng][row_local][class]
    float* cpart = (float*)(sm + OFF_CP);
    if ((lane & 3) == 0) {
#pragma unroll
        for (int at = 0; at < 2; at++) {
            const int rl = mt * 32 + at * 16 + (lane >> 2);
#pragma unroll
            for (int c = 0; c < 4; c++) {
                cpart[(ng * 64 + rl) * 4 + c]     = p[at][0][c];
                cpart[(ng * 64 + rl + 8) * 4 + c] = p[at][1][c];
            }
        }
    }
    __syncthreads();
    {
        const int rl = tid >> 2, c = tid & 3;   // 64 rows x 4 classes
        const int r = R0 + rl;
        if (r < n) {
            const float* bcp = (const float*)(sm + OFF_BC);
            out[(size_t)r * 4 + c] =
                ((cpart[rl * 4 + c] + cpart[(64 + rl) * 4 + c]) +
                 (cpart[(128 + rl) * 4 + c] + cpart[(192 + rl) * 4 + c])) + bcp[c];
        }
    }
}

// ---------------------------------------------------------------------------
extern "C" void kernel_launch(void* const* d_in, const int* in_sizes, int n_in,
                              void* d_out, int out_size)
{
    const float* x  = (const float*)d_in[0];
    const int*   ei = (const int*)  d_in[1];
    const float* W0 = (const float*)d_in[2];
    const float* b0 = (const float*)d_in[3];
    const float* W1 = (const float*)d_in[4];
    const float* b1 = (const float*)d_in[5];
    const float* Wc = (const float*)d_in[6];
    const float* bc = (const float*)d_in[7];
    float* out = (float*)d_out;

    const int n       = in_sizes[0] / DIM;
    const int n_edges = in_sizes[1] / 2;

    void *aggp, *degp, *hp;
    cudaGetSymbolAddress(&aggp, g_agg);
    cudaGetSymbolAddress(&degp, g_deg);
    cudaGetSymbolAddress(&hp,   g_h);

    cudaFuncSetAttribute(gemm0_mma, cudaFuncAttributeMaxDynamicSharedMemorySize, SMEM_BYTES);
    cudaFuncSetAttribute(gemm1_mma, cudaFuncAttributeMaxDynamicSharedMemorySize, SMEM_BYTES);

    cudaMemsetAsync(aggp, 0, (size_t)n * DIM * sizeof(float));
    cudaMemsetAsync(degp, 0, (size_t)n * sizeof(float));

    const int gblocks = (n + 63) / 64;
    gemm0_mma<<<gblocks, 256, SMEM_BYTES>>>(x, W0, b0, (float*)hp, n);
    scatter_kernel<<<(n_edges + 7) / 8, 256>>>(ei, n_edges);
    gemm1_mma<<<gblocks, 256, SMEM_BYTES>>>(W1, b1, Wc, bc, out, n);
}